// round 16
// baseline (speedup 1.0000x reference)
#include <cuda_runtime.h>
#include <cuda_fp16.h>
#include <math_constants.h>
#include <math.h>
#include <stdint.h>

#define BSZ   8
#define TSEQ  1024
#define EMB   1024
#define NHEAD 16
#define HEADD 64
#define MROWS (BSZ * TSEQ)   // 8192
#define FFDIM 4096
#define QKV_N 3072

// ---------------------------------------------------------------------------
// Scratch
// ---------------------------------------------------------------------------
__device__ __half g_h    [(size_t)MROWS * EMB];
__device__ __half g_xh   [(size_t)MROWS * EMB];   // fp16 copy of x
__device__ __half g_qkv  [(size_t)MROWS * QKV_N];
__device__ __half g_attn [(size_t)MROWS * EMB];
__device__ __half g_out1 [(size_t)MROWS * EMB];   // fp16 residual
__device__ __half g_mid  [(size_t)MROWS * FFDIM];
__device__ __half g_wqkvT[(size_t)QKV_N * EMB];
__device__ __half g_wpT  [(size_t)EMB * EMB];
__device__ __half g_w1T  [(size_t)EMB * FFDIM];
__device__ __half g_w2T  [(size_t)FFDIM * EMB];

// ---------------------------------------------------------------------------
// Helpers
// ---------------------------------------------------------------------------
__device__ __forceinline__ uint32_t smem_u32(const void* p) {
    uint32_t a;
    asm("{ .reg .u64 t; cvta.to.shared.u64 t, %1; cvt.u32.u64 %0, t; }" : "=r"(a) : "l"(p));
    return a;
}

__device__ __forceinline__ void cp16(uint32_t dst, const void* src) {
    asm volatile("cp.async.cg.shared.global [%0], [%1], 16;" :: "r"(dst), "l"(src) : "memory");
}
__device__ __forceinline__ void cp_commit() {
    asm volatile("cp.async.commit_group;" ::: "memory");
}
template<int N>
__device__ __forceinline__ void cp_wait() {
    asm volatile("cp.async.wait_group %0;" :: "n"(N) : "memory");
}

__device__ __forceinline__ void ldsm_x4(uint32_t& r0, uint32_t& r1, uint32_t& r2, uint32_t& r3,
                                        uint32_t addr) {
    asm volatile("ldmatrix.sync.aligned.m8n8.x4.shared.b16 {%0,%1,%2,%3}, [%4];"
                 : "=r"(r0), "=r"(r1), "=r"(r2), "=r"(r3) : "r"(addr));
}
__device__ __forceinline__ void ldsm_x4t(uint32_t& r0, uint32_t& r1, uint32_t& r2, uint32_t& r3,
                                         uint32_t addr) {
    asm volatile("ldmatrix.sync.aligned.m8n8.x4.trans.shared.b16 {%0,%1,%2,%3}, [%4];"
                 : "=r"(r0), "=r"(r1), "=r"(r2), "=r"(r3) : "r"(addr));
}

__device__ __forceinline__ void mma_f16(float& c0, float& c1, float& c2, float& c3,
                                        uint32_t a0, uint32_t a1, uint32_t a2, uint32_t a3,
                                        uint32_t b0, uint32_t b1) {
    asm volatile(
        "mma.sync.aligned.m16n8k16.row.col.f32.f16.f16.f32 "
        "{%0,%1,%2,%3}, {%4,%5,%6,%7}, {%8,%9}, {%0,%1,%2,%3};"
        : "+f"(c0), "+f"(c1), "+f"(c2), "+f"(c3)
        : "r"(a0), "r"(a1), "r"(a2), "r"(a3), "r"(b0), "r"(b1));
}

// Fast GELU: tanh-form with HW tanh.approx
__device__ __forceinline__ float gelu_fast(float x) {
    float u = x * (0.7978845608028654f + 0.035677408136300125f * x * x);
    float t;
    asm("tanh.approx.f32 %0, %1;" : "=f"(t) : "f"(u));
    return 0.5f * x * (1.0f + t);
}

// ---------------------------------------------------------------------------
// Fused prep: 6 weight transposes + LN1 (+ fp16 copy of x), one launch.
// ---------------------------------------------------------------------------
struct PrepArgs {
    const float* in[6];
    __half*      out[6];
    int K[6], N[6];
    int off[6];
    int trans_total;
};

__global__ __launch_bounds__(256)
void prep_kernel(PrepArgs A, const float* __restrict__ x, const float* __restrict__ lg,
                 const float* __restrict__ lb, __half* __restrict__ lnout,
                 __half* __restrict__ xh)
{
    int blk = blockIdx.x;
    int tid = threadIdx.x;

    if (blk < A.trans_total) {
        __shared__ float t[32][33];
        int m = 0;
        #pragma unroll
        for (int i = 1; i < 6; i++) if (blk >= A.off[i]) m = i;
        int lt = blk - A.off[m];
        int N = A.N[m], K = A.K[m];
        int ntx = N >> 5;
        int n0 = (lt % ntx) * 32, k0 = (lt / ntx) * 32;
        const float* in = A.in[m];
        __half* out = A.out[m];
        int tx = tid & 31, ty = tid >> 5;
        #pragma unroll
        for (int i = 0; i < 32; i += 8)
            t[ty + i][tx] = in[(size_t)(k0 + ty + i) * N + n0 + tx];
        __syncthreads();
        #pragma unroll
        for (int i = 0; i < 32; i += 8)
            out[(size_t)(n0 + ty + i) * K + k0 + tx] = __float2half_rn(t[tx][ty + i]);
        return;
    }

    int row = blk - A.trans_total;
    const float4* xr = (const float4*)(x + (size_t)row * EMB);
    float4 v = xr[tid];
    // fp16 copy of x for residual use
    __half2* xrow = (__half2*)(xh + (size_t)row * EMB);
    xrow[2 * tid]     = __floats2half2_rn(v.x, v.y);
    xrow[2 * tid + 1] = __floats2half2_rn(v.z, v.w);

    float s  = v.x + v.y + v.z + v.w;
    float ss = v.x * v.x + v.y * v.y + v.z * v.z + v.w * v.w;
    #pragma unroll
    for (int o = 16; o; o >>= 1) {
        s  += __shfl_xor_sync(0xffffffffu, s,  o);
        ss += __shfl_xor_sync(0xffffffffu, ss, o);
    }
    __shared__ float rs_[8], rss_[8];
    __shared__ float mu_s, rstd_s;
    int warp = tid >> 5, lane = tid & 31;
    if (lane == 0) { rs_[warp] = s; rss_[warp] = ss; }
    __syncthreads();
    if (tid == 0) {
        float S = 0.f, SS = 0.f;
        #pragma unroll
        for (int i = 0; i < 8; i++) { S += rs_[i]; SS += rss_[i]; }
        float mu  = S * (1.0f / EMB);
        float var = SS * (1.0f / EMB) - mu * mu;
        mu_s = mu;
        rstd_s = rsqrtf(var + 1e-5f);
    }
    __syncthreads();
    float mu = mu_s, r = rstd_s;
    float4 gv = ((const float4*)lg)[tid];
    float4 bv = ((const float4*)lb)[tid];
    __half2* orow = (__half2*)(lnout + (size_t)row * EMB);
    orow[2 * tid]     = __floats2half2_rn((v.x - mu) * r * gv.x + bv.x,
                                          (v.y - mu) * r * gv.y + bv.y);
    orow[2 * tid + 1] = __floats2half2_rn((v.z - mu) * r * gv.z + bv.z,
                                          (v.w - mu) * r * gv.w + bv.w);
}

// ---------------------------------------------------------------------------
// LayerNorm for LN2: HALF in -> half out
// ---------------------------------------------------------------------------
__global__ __launch_bounds__(256)
void ln_h_kernel(const __half* __restrict__ x, const float* __restrict__ g,
                 const float* __restrict__ b, __half* __restrict__ out)
{
    int row = blockIdx.x;
    int t   = threadIdx.x;
    const float4* xr = (const float4*)(x + (size_t)row * EMB);  // 8 halves
    float4 raw = xr[t >> 1];
    // each thread handles 4 halves: t even -> first 4, t odd -> last 4
    __half2 h0 = ((__half2*)&raw)[(t & 1) * 2];
    __half2 h1 = ((__half2*)&raw)[(t & 1) * 2 + 1];
    float2 f0 = __half22float2(h0);
    float2 f1 = __half22float2(h1);
    float vx = f0.x, vy = f0.y, vz = f1.x, vw = f1.y;

    float s  = vx + vy + vz + vw;
    float ss = vx * vx + vy * vy + vz * vz + vw * vw;
    #pragma unroll
    for (int o = 16; o; o >>= 1) {
        s  += __shfl_xor_sync(0xffffffffu, s,  o);
        ss += __shfl_xor_sync(0xffffffffu, ss, o);
    }
    __shared__ float rs_[8], rss_[8];
    __shared__ float mu_s, rstd_s;
    int warp = t >> 5, lane = t & 31;
    if (lane == 0) { rs_[warp] = s; rss_[warp] = ss; }
    __syncthreads();
    if (t == 0) {
        float S = 0.f, SS = 0.f;
        #pragma unroll
        for (int i = 0; i < 8; i++) { S += rs_[i]; SS += rss_[i]; }
        float mu  = S * (1.0f / EMB);
        float var = SS * (1.0f / EMB) - mu * mu;
        mu_s = mu;
        rstd_s = rsqrtf(var + 1e-5f);
    }
    __syncthreads();
    float mu = mu_s, r = rstd_s;
    float4 gv = ((const float4*)g)[t];
    float4 bv = ((const float4*)b)[t];
    __half2* orow = (__half2*)(out + (size_t)row * EMB);
    orow[2 * t]     = __floats2half2_rn((vx - mu) * r * gv.x + bv.x,
                                        (vy - mu) * r * gv.y + bv.y);
    orow[2 * t + 1] = __floats2half2_rn((vz - mu) * r * gv.z + bv.z,
                                        (vw - mu) * r * gv.w + bv.w);
}

// ---------------------------------------------------------------------------
// fp16 mma GEMM: CTA 128x128, 256 threads (8 warps, warp tile 64x32),
// BK=64, 3-stage cp.async, ONE barrier per chunk, 2 CTAs/SM.
// Residual operand (if any) is HALF.
// ---------------------------------------------------------------------------
#define G5_STRIDE 72
#define G5_ATILE (128 * G5_STRIDE * 2)   // 18432 B
#define G5_STAGE (2 * G5_ATILE)          // 36864 B (A+B)
#define G5_SMEM  (3 * G5_STAGE)          // 110592 B -> 2 CTAs/SM

template<bool GELU, bool HALF_OUT>
__global__ __launch_bounds__(256, 2)
void gemm_h_kernel(const __half* __restrict__ A, const __half* __restrict__ Bt,
                   const float* __restrict__ bias, const __half* __restrict__ res,
                   void* __restrict__ Cv, int N_, int K_)
{
    extern __shared__ char smem[];
    const uint32_t sb = smem_u32(smem);
    int tid  = threadIdx.x;
    int lane = tid & 31, warp = tid >> 5;
    int wm = warp >> 2;
    int wn = warp & 3;
    int rowBase = blockIdx.y * 128;
    int colBase = blockIdx.x * 128;
    const int C_CHUNKS = K_ >> 6;

    auto load_chunk = [&](int c, int st) {
        int k0 = c << 6;
        uint32_t aB = sb + st * G5_STAGE;
        uint32_t bB = aB + G5_ATILE;
        #pragma unroll
        for (int s = 0; s < 4; s++) {
            int idx = tid + s * 256;
            int r = idx >> 3, ch = idx & 7;
            cp16(aB + (uint32_t)(r * G5_STRIDE + ch * 8) * 2,
                 A + (size_t)(rowBase + r) * K_ + k0 + ch * 8);
        }
        #pragma unroll
        for (int s = 0; s < 4; s++) {
            int idx = tid + s * 256;
            int r = idx >> 3, ch = idx & 7;
            cp16(bB + (uint32_t)(r * G5_STRIDE + ch * 8) * 2,
                 Bt + (size_t)(colBase + r) * K_ + k0 + ch * 8);
        }
        cp_commit();
    };

    float acc[4][4][4];
    #pragma unroll
    for (int i = 0; i < 4; i++)
        #pragma unroll
        for (int j = 0; j < 4; j++)
            #pragma unroll
            for (int r = 0; r < 4; r++) acc[i][j][r] = 0.f;

    load_chunk(0, 0);
    load_chunk(1, 1);

    for (int c = 0; c < C_CHUNKS; c++) {
        cp_wait<1>();
        __syncthreads();
        if (c + 2 < C_CHUNKS) load_chunk(c + 2, (c + 2) % 3);
        else cp_commit();

        uint32_t aBase = sb + (c % 3) * G5_STAGE;
        uint32_t bBase = aBase + G5_ATILE;

        #pragma unroll
        for (int ks = 0; ks < 4; ks++) {
            int k0 = ks * 16;
            uint32_t a[4][4];
            #pragma unroll
            for (int mt = 0; mt < 4; mt++) {
                uint32_t addr = aBase +
                    (uint32_t)((wm * 64 + mt * 16 + (lane & 15)) * G5_STRIDE
                               + k0 + ((lane >> 4) << 3)) * 2;
                ldsm_x4(a[mt][0], a[mt][1], a[mt][2], a[mt][3], addr);
            }
            uint32_t bf[4][2];
            {
                int n = wn * 32 + ((lane >> 4) << 3) + (lane & 7);
                int koff = ((lane >> 3) & 1) << 3;
                ldsm_x4(bf[0][0], bf[0][1], bf[1][0], bf[1][1],
                        bBase + (uint32_t)(n * G5_STRIDE + k0 + koff) * 2);
                ldsm_x4(bf[2][0], bf[2][1], bf[3][0], bf[3][1],
                        bBase + (uint32_t)((n + 16) * G5_STRIDE + k0 + koff) * 2);
            }
            #pragma unroll
            for (int mt = 0; mt < 4; mt++)
                #pragma unroll
                for (int nt = 0; nt < 4; nt++)
                    mma_f16(acc[mt][nt][0], acc[mt][nt][1], acc[mt][nt][2], acc[mt][nt][3],
                            a[mt][0], a[mt][1], a[mt][2], a[mt][3],
                            bf[nt][0], bf[nt][1]);
        }
    }

    int lq = lane >> 2, lr = lane & 3;
    __half* Ch = (__half*)Cv;
    float*  Cf = (float*)Cv;
    #pragma unroll
    for (int mt = 0; mt < 4; mt++) {
        int row0 = rowBase + wm * 64 + mt * 16 + lq;
        #pragma unroll
        for (int nt = 0; nt < 4; nt++) {
            int col = colBase + wn * 32 + nt * 8 + lr * 2;
            float2 p0 = make_float2(acc[mt][nt][0], acc[mt][nt][1]);
            float2 p1 = make_float2(acc[mt][nt][2], acc[mt][nt][3]);
            if (bias) {
                float2 bv = *(const float2*)(bias + col);
                p0.x += bv.x; p0.y += bv.y;
                p1.x += bv.x; p1.y += bv.y;
            }
            if (res) {
                float2 r0 = __half22float2(*(const __half2*)(res + (size_t)row0 * N_ + col));
                float2 r1 = __half22float2(*(const __half2*)(res + (size_t)(row0 + 8) * N_ + col));
                p0.x += r0.x; p0.y += r0.y;
                p1.x += r1.x; p1.y += r1.y;
            }
            if (GELU) {
                p0.x = gelu_fast(p0.x);
                p0.y = gelu_fast(p0.y);
                p1.x = gelu_fast(p1.x);
                p1.y = gelu_fast(p1.y);
            }
            if (HALF_OUT) {
                *(__half2*)(Ch + (size_t)row0 * N_ + col) = __floats2half2_rn(p0.x, p0.y);
                *(__half2*)(Ch + (size_t)(row0 + 8) * N_ + col) = __floats2half2_rn(p1.x, p1.y);
            } else {
                *(float2*)(Cf + (size_t)row0 * N_ + col) = p0;
                *(float2*)(Cf + (size_t)(row0 + 8) * N_ + col) = p1;
            }
        }
    }
}

// ---------------------------------------------------------------------------
// fp16 flash attention, cp.async double-buffered K/V, 2 Q-tiles per CTA.
// ---------------------------------------------------------------------------
#define AHS 72
#define AKV (64 * AHS)
#define AH_SMEM (6 * AKV * 2)             // 55296 B

__global__ __launch_bounds__(128, 2)
void attn_h_kernel(const __half* __restrict__ QKV, __half* __restrict__ Out)
{
    extern __shared__ char smraw[];
    __half* sm = (__half*)smraw;
    __half* Qs = sm;
    __half* Ks = sm + AKV;
    __half* Vs = sm + 3 * AKV;
    __half* Ps = sm + 5 * AKV;
    const uint32_t sQ = smem_u32(Qs), sK0 = smem_u32(Ks), sV0 = smem_u32(Vs),
                   sP = smem_u32(Ps);

    int qb0 = blockIdx.x, h = blockIdx.y, bb = blockIdx.z;
    int tid = threadIdx.x;
    int lane = tid & 31, warp = tid >> 5;
    int lq = lane >> 2, lr = lane & 3;

    const __half* Qp = QKV + h * HEADD;
    const __half* Kp = QKV + EMB + h * HEADD;
    const __half* Vp = QKV + 2 * EMB + h * HEADD;

    auto load_kv = [&](int jt, int b) {
        size_t kbase = (size_t)(bb * TSEQ + jt * 64) * QKV_N;
        uint32_t kB = sK0 + (uint32_t)(b * AKV) * 2;
        uint32_t vB = sV0 + (uint32_t)(b * AKV) * 2;
        #pragma unroll
        for (int s = 0; s < 4; s++) {
            int idx = tid + s * 128;
            int r = idx >> 3, ch = idx & 7;
            cp16(kB + (uint32_t)(r * AHS + ch * 8) * 2,
                 Kp + kbase + (size_t)r * QKV_N + ch * 8);
            cp16(vB + (uint32_t)(r * AHS + ch * 8) * 2,
                 Vp + kbase + (size_t)r * QKV_N + ch * 8);
        }
        cp_commit();
    };

    const uint32_t sPw = sP + (uint32_t)(warp * 16 * AHS) * 2;
    __half* prow = Ps + warp * 16 * AHS;

    #pragma unroll
    for (int rep = 0; rep < 2; rep++) {
        int qb = rep ? (TSEQ / 64 - 1 - qb0) : qb0;

        __syncthreads();

        size_t qbase = (size_t)(bb * TSEQ + qb * 64) * QKV_N;
        #pragma unroll
        for (int s = 0; s < 4; s++) {
            int idx = tid + s * 128;
            int r = idx >> 3, ch = idx & 7;
            *(float4*)(Qs + r * AHS + ch * 8) =
                *(const float4*)(Qp + qbase + (size_t)r * QKV_N + ch * 8);
        }
        load_kv(0, 0);

        float m0 = -CUDART_INF_F, m1 = -CUDART_INF_F;
        float l0 = 0.f, l1 = 0.f;
        float o[8][4];
        #pragma unroll
        for (int nt = 0; nt < 8; nt++)
            #pragma unroll
            for (int r = 0; r < 4; r++) o[nt][r] = 0.f;

        for (int jt = 0; jt <= qb; jt++) {
            cp_wait<0>();
            __syncthreads();
            if (jt < qb) load_kv(jt + 1, (jt + 1) & 1);

            uint32_t sK = sK0 + (uint32_t)((jt & 1) * AKV) * 2;
            uint32_t sV = sV0 + (uint32_t)((jt & 1) * AKV) * 2;

            float s[8][4];
            #pragma unroll
            for (int nt = 0; nt < 8; nt++)
                #pragma unroll
                for (int r = 0; r < 4; r++) s[nt][r] = 0.f;

            #pragma unroll
            for (int ks = 0; ks < 4; ks++) {
                int k0 = ks * 16;
                uint32_t a0, a1, a2, a3;
                ldsm_x4(a0, a1, a2, a3,
                        sQ + (uint32_t)((warp * 16 + (lane & 15)) * AHS
                                        + k0 + ((lane >> 4) << 3)) * 2);
                #pragma unroll
                for (int np = 0; np < 4; np++) {
                    int n = np * 16 + ((lane >> 4) << 3) + (lane & 7);
                    int koff = ((lane >> 3) & 1) << 3;
                    uint32_t b0, b1, b2, b3;
                    ldsm_x4(b0, b1, b2, b3,
                            sK + (uint32_t)(n * AHS + k0 + koff) * 2);
                    mma_f16(s[np * 2][0], s[np * 2][1], s[np * 2][2], s[np * 2][3],
                            a0, a1, a2, a3, b0, b1);
                    mma_f16(s[np * 2 + 1][0], s[np * 2 + 1][1], s[np * 2 + 1][2], s[np * 2 + 1][3],
                            a0, a1, a2, a3, b2, b3);
                }
            }

            const float scale = 0.125f;
            bool diag = (jt == qb);
            int row0 = warp * 16 + lq;
            #pragma unroll
            for (int nt = 0; nt < 8; nt++) {
                int col = nt * 8 + 2 * lr;
                s[nt][0] *= scale; s[nt][1] *= scale;
                s[nt][2] *= scale; s[nt][3] *= scale;
                if (diag) {
                    if (col     > row0)     s[nt][0] = -CUDART_INF_F;
                    if (col + 1 > row0)     s[nt][1] = -CUDART_INF_F;
                    if (col     > row0 + 8) s[nt][2] = -CUDART_INF_F;
                    if (col + 1 > row0 + 8) s[nt][3] = -CUDART_INF_F;
                }
            }

            {
                float rm = -CUDART_INF_F;
                #pragma unroll
                for (int nt = 0; nt < 8; nt++) rm = fmaxf(rm, fmaxf(s[nt][0], s[nt][1]));
                rm = fmaxf(rm, __shfl_xor_sync(0xffffffffu, rm, 1));
                rm = fmaxf(rm, __shfl_xor_sync(0xffffffffu, rm, 2));
                float mn = fmaxf(m0, rm);
                float alpha = __expf(m0 - mn);
                float ps = 0.f;
                #pragma unroll
                for (int nt = 0; nt < 8; nt++) {
                    s[nt][0] = __expf(s[nt][0] - mn);
                    s[nt][1] = __expf(s[nt][1] - mn);
                    ps += s[nt][0] + s[nt][1];
                }
                ps += __shfl_xor_sync(0xffffffffu, ps, 1);
                ps += __shfl_xor_sync(0xffffffffu, ps, 2);
                l0 = l0 * alpha + ps;
                m0 = mn;
                #pragma unroll
                for (int nt = 0; nt < 8; nt++) { o[nt][0] *= alpha; o[nt][1] *= alpha; }
            }
            {
                float rm = -CUDART_INF_F;
                #pragma unroll
                for (int nt = 0; nt < 8; nt++) rm = fmaxf(rm, fmaxf(s[nt][2], s[nt][3]));
                rm = fmaxf(rm, __shfl_xor_sync(0xffffffffu, rm, 1));
                rm = fmaxf(rm, __shfl_xor_sync(0xffffffffu, rm, 2));
                float mn = fmaxf(m1, rm);
                float alpha = __expf(m1 - mn);
                float ps = 0.f;
                #pragma unroll
                for (int nt = 0; nt < 8; nt++) {
                    s[nt][2] = __expf(s[nt][2] - mn);
                    s[nt][3] = __expf(s[nt][3] - mn);
                    ps += s[nt][2] + s[nt][3];
                }
                ps += __shfl_xor_sync(0xffffffffu, ps, 1);
                ps += __shfl_xor_sync(0xffffffffu, ps, 2);
                l1 = l1 * alpha + ps;
                m1 = mn;
                #pragma unroll
                for (int nt = 0; nt < 8; nt++) { o[nt][2] *= alpha; o[nt][3] *= alpha; }
            }

            #pragma unroll
            for (int nt = 0; nt < 8; nt++) {
                *(__half2*)(prow + lq * AHS + nt * 8 + 2 * lr) =
                    __floats2half2_rn(s[nt][0], s[nt][1]);
                *(__half2*)(prow + (lq + 8) * AHS + nt * 8 + 2 * lr) =
                    __floats2half2_rn(s[nt][2], s[nt][3]);
            }
            __syncwarp();

            #pragma unroll
            for (int ks = 0; ks < 4; ks++) {
                int k0 = ks * 16;
                uint32_t a0, a1, a2, a3;
                ldsm_x4(a0, a1, a2, a3,
                        sPw + (uint32_t)((lane & 15) * AHS + k0 + ((lane >> 4) << 3)) * 2);
                #pragma unroll
                for (int dp = 0; dp < 4; dp++) {
                    uint32_t b0, b1, b2, b3;
                    ldsm_x4t(b0, b1, b2, b3,
                             sV + (uint32_t)((k0 + (lane & 15)) * AHS
                                             + dp * 16 + ((lane >> 4) << 3)) * 2);
                    mma_f16(o[dp * 2][0], o[dp * 2][1], o[dp * 2][2], o[dp * 2][3],
                            a0, a1, a2, a3, b0, b1);
                    mma_f16(o[dp * 2 + 1][0], o[dp * 2 + 1][1], o[dp * 2 + 1][2], o[dp * 2 + 1][3],
                            a0, a1, a2, a3, b2, b3);
                }
            }
            __syncwarp();
        }

        float inv0 = 1.0f / l0, inv1 = 1.0f / l1;
        size_t r0 = (size_t)(bb * TSEQ + qb * 64 + warp * 16 + lq);
        size_t r1 = r0 + 8;
        #pragma unroll
        for (int nt = 0; nt < 8; nt++) {
            int col = h * HEADD + nt * 8 + 2 * lr;
            *(__half2*)(Out + r0 * EMB + col) =
                __floats2half2_rn(o[nt][0] * inv0, o[nt][1] * inv0);
            *(__half2*)(Out + r1 * EMB + col) =
                __floats2half2_rn(o[nt][2] * inv1, o[nt][3] * inv1);
        }
    }
}

// ---------------------------------------------------------------------------
// Launch
// ---------------------------------------------------------------------------
extern "C" void kernel_launch(void* const* d_in, const int* in_sizes, int n_in,
                              void* d_out, int out_size)
{
    const float* x      = (const float*)d_in[0];
    const float* ln1_g  = (const float*)d_in[1];
    const float* ln1_b  = (const float*)d_in[2];
    const float* wq     = (const float*)d_in[3];
    const float* wk     = (const float*)d_in[4];
    const float* wv     = (const float*)d_in[5];
    const float* w_proj = (const float*)d_in[6];
    const float* b_proj = (const float*)d_in[7];
    const float* ln2_g  = (const float*)d_in[8];
    const float* ln2_b  = (const float*)d_in[9];
    const float* w1     = (const float*)d_in[10];
    const float* b1     = (const float*)d_in[11];
    const float* w2     = (const float*)d_in[12];
    const float* b2     = (const float*)d_in[13];
    float* out = (float*)d_out;

    __half *h, *xh, *qkv, *attn, *out1, *mid;
    __half *wqkvT, *wpT, *w1T, *w2T;
    cudaGetSymbolAddress((void**)&h,     g_h);
    cudaGetSymbolAddress((void**)&xh,    g_xh);
    cudaGetSymbolAddress((void**)&qkv,   g_qkv);
    cudaGetSymbolAddress((void**)&attn,  g_attn);
    cudaGetSymbolAddress((void**)&out1,  g_out1);
    cudaGetSymbolAddress((void**)&mid,   g_mid);
    cudaGetSymbolAddress((void**)&wqkvT, g_wqkvT);
    cudaGetSymbolAddress((void**)&wpT,   g_wpT);
    cudaGetSymbolAddress((void**)&w1T,   g_w1T);
    cudaGetSymbolAddress((void**)&w2T,   g_w2T);

    cudaFuncSetAttribute(gemm_h_kernel<false, false>,
                         cudaFuncAttributeMaxDynamicSharedMemorySize, G5_SMEM);
    cudaFuncSetAttribute(gemm_h_kernel<false, true>,
                         cudaFuncAttributeMaxDynamicSharedMemorySize, G5_SMEM);
    cudaFuncSetAttribute(gemm_h_kernel<true, true>,
                         cudaFuncAttributeMaxDynamicSharedMemorySize, G5_SMEM);
    cudaFuncSetAttribute(attn_h_kernel,
                         cudaFuncAttributeMaxDynamicSharedMemorySize, AH_SMEM);

    // 0. Prep: 6 transposes + LN1 + x->fp16 in one launch
    PrepArgs pa;
    pa.in[0] = wq;     pa.out[0] = wqkvT;                         pa.K[0] = EMB;   pa.N[0] = EMB;
    pa.in[1] = wk;     pa.out[1] = wqkvT + (size_t)EMB * EMB;     pa.K[1] = EMB;   pa.N[1] = EMB;
    pa.in[2] = wv;     pa.out[2] = wqkvT + (size_t)2 * EMB * EMB; pa.K[2] = EMB;   pa.N[2] = EMB;
    pa.in[3] = w_proj; pa.out[3] = wpT;                           pa.K[3] = EMB;   pa.N[3] = EMB;
    pa.in[4] = w1;     pa.out[4] = w1T;                           pa.K[4] = EMB;   pa.N[4] = FFDIM;
    pa.in[5] = w2;     pa.out[5] = w2T;                           pa.K[5] = FFDIM; pa.N[5] = EMB;
    int total = 0;
    for (int i = 0; i < 6; i++) {
        pa.off[i] = total;
        total += (pa.N[i] / 32) * (pa.K[i] / 32);
    }
    pa.trans_total = total;
    prep_kernel<<<total + MROWS, 256>>>(pa, x, ln1_g, ln1_b, h, xh);

    // 2. Fused QKV projection
    dim3 gQKV(QKV_N / 128, MROWS / 128);
    gemm_h_kernel<false, true><<<gQKV, 256, G5_SMEM>>>(h, wqkvT, nullptr, nullptr, qkv, QKV_N, EMB);

    // 3. Causal flash attention
    attn_h_kernel<<<dim3(TSEQ / 128, NHEAD, BSZ), 128, AH_SMEM>>>(qkv, attn);

    // 4. out1 = x + attn @ w_proj + b_proj  (fp16 residual in, fp16 out)
    dim3 gE(EMB / 128, MROWS / 128);
    gemm_h_kernel<false, true><<<gE, 256, G5_SMEM>>>(attn, wpT, b_proj, xh, out1, EMB, EMB);

    // 5. LN2 (half in, half out)
    ln_h_kernel<<<MROWS, 256>>>(out1, ln2_g, ln2_b, h);

    // 6. mid = gelu(h @ w1 + b1)
    dim3 gF(FFDIM / 128, MROWS / 128);
    gemm_h_kernel<true, true><<<gF, 256, G5_SMEM>>>(h, w1T, b1, nullptr, mid, FFDIM, EMB);

    // 7. out = out1 + mid @ w2 + b2  (fp16 residual in, fp32 out)
    gemm_h_kernel<false, false><<<gE, 256, G5_SMEM>>>(mid, w2T, b2, out1, out, EMB, FFDIM);
}

// round 17
// speedup vs baseline: 1.5501x; 1.5501x over previous
#include <cuda_runtime.h>
#include <cuda_fp16.h>
#include <math_constants.h>
#include <math.h>
#include <stdint.h>

#define BSZ   8
#define TSEQ  1024
#define EMB   1024
#define NHEAD 16
#define HEADD 64
#define MROWS (BSZ * TSEQ)   // 8192
#define FFDIM 4096
#define QKV_N 3072

// ---------------------------------------------------------------------------
// Scratch
// ---------------------------------------------------------------------------
__device__ __half g_h    [(size_t)MROWS * EMB];
__device__ __half g_qkv  [(size_t)MROWS * QKV_N];
__device__ __half g_attn [(size_t)MROWS * EMB];
__device__ float  g_out1 [(size_t)MROWS * EMB];
__device__ __half g_mid  [(size_t)MROWS * FFDIM];
__device__ __half g_wqkvT[(size_t)QKV_N * EMB];
__device__ __half g_wpT  [(size_t)EMB * EMB];
__device__ __half g_w1T  [(size_t)EMB * FFDIM];
__device__ __half g_w2T  [(size_t)FFDIM * EMB];

// ---------------------------------------------------------------------------
// Helpers
// ---------------------------------------------------------------------------
__device__ __forceinline__ uint32_t smem_u32(const void* p) {
    uint32_t a;
    asm("{ .reg .u64 t; cvta.to.shared.u64 t, %1; cvt.u32.u64 %0, t; }" : "=r"(a) : "l"(p));
    return a;
}

__device__ __forceinline__ void cp16(uint32_t dst, const void* src) {
    asm volatile("cp.async.cg.shared.global [%0], [%1], 16;" :: "r"(dst), "l"(src) : "memory");
}
__device__ __forceinline__ void cp_commit() {
    asm volatile("cp.async.commit_group;" ::: "memory");
}
template<int N>
__device__ __forceinline__ void cp_wait() {
    asm volatile("cp.async.wait_group %0;" :: "n"(N) : "memory");
}

__device__ __forceinline__ void ldsm_x4(uint32_t& r0, uint32_t& r1, uint32_t& r2, uint32_t& r3,
                                        uint32_t addr) {
    asm volatile("ldmatrix.sync.aligned.m8n8.x4.shared.b16 {%0,%1,%2,%3}, [%4];"
                 : "=r"(r0), "=r"(r1), "=r"(r2), "=r"(r3) : "r"(addr));
}
__device__ __forceinline__ void ldsm_x4t(uint32_t& r0, uint32_t& r1, uint32_t& r2, uint32_t& r3,
                                         uint32_t addr) {
    asm volatile("ldmatrix.sync.aligned.m8n8.x4.trans.shared.b16 {%0,%1,%2,%3}, [%4];"
                 : "=r"(r0), "=r"(r1), "=r"(r2), "=r"(r3) : "r"(addr));
}

__device__ __forceinline__ void mma_f16(float& c0, float& c1, float& c2, float& c3,
                                        uint32_t a0, uint32_t a1, uint32_t a2, uint32_t a3,
                                        uint32_t b0, uint32_t b1) {
    asm volatile(
        "mma.sync.aligned.m16n8k16.row.col.f32.f16.f16.f32 "
        "{%0,%1,%2,%3}, {%4,%5,%6,%7}, {%8,%9}, {%0,%1,%2,%3};"
        : "+f"(c0), "+f"(c1), "+f"(c2), "+f"(c3)
        : "r"(a0), "r"(a1), "r"(a2), "r"(a3), "r"(b0), "r"(b1));
}

// Fast GELU: tanh-form with HW tanh.approx
__device__ __forceinline__ float gelu_fast(float x) {
    float u = x * (0.7978845608028654f + 0.035677408136300125f * x * x);
    float t;
    asm("tanh.approx.f32 %0, %1;" : "=f"(t) : "f"(u));
    return 0.5f * x * (1.0f + t);
}

// ---------------------------------------------------------------------------
// Fused prep: 6 weight transposes + LN1, one launch.
// ---------------------------------------------------------------------------
struct PrepArgs {
    const float* in[6];
    __half*      out[6];
    int K[6], N[6];
    int off[6];
    int trans_total;
};

__global__ __launch_bounds__(256)
void prep_kernel(PrepArgs A, const float* __restrict__ x, const float* __restrict__ lg,
                 const float* __restrict__ lb, __half* __restrict__ lnout)
{
    int blk = blockIdx.x;
    int tid = threadIdx.x;

    if (blk < A.trans_total) {
        __shared__ float t[32][33];
        int m = 0;
        #pragma unroll
        for (int i = 1; i < 6; i++) if (blk >= A.off[i]) m = i;
        int lt = blk - A.off[m];
        int N = A.N[m], K = A.K[m];
        int ntx = N >> 5;
        int n0 = (lt % ntx) * 32, k0 = (lt / ntx) * 32;
        const float* in = A.in[m];
        __half* out = A.out[m];
        int tx = tid & 31, ty = tid >> 5;
        #pragma unroll
        for (int i = 0; i < 32; i += 8)
            t[ty + i][tx] = in[(size_t)(k0 + ty + i) * N + n0 + tx];
        __syncthreads();
        #pragma unroll
        for (int i = 0; i < 32; i += 8)
            out[(size_t)(n0 + ty + i) * K + k0 + tx] = __float2half_rn(t[tx][ty + i]);
        return;
    }

    int row = blk - A.trans_total;
    const float4* xr = (const float4*)(x + (size_t)row * EMB);
    float4 v = xr[tid];
    float s  = v.x + v.y + v.z + v.w;
    float ss = v.x * v.x + v.y * v.y + v.z * v.z + v.w * v.w;
    #pragma unroll
    for (int o = 16; o; o >>= 1) {
        s  += __shfl_xor_sync(0xffffffffu, s,  o);
        ss += __shfl_xor_sync(0xffffffffu, ss, o);
    }
    __shared__ float rs_[8], rss_[8];
    __shared__ float mu_s, rstd_s;
    int warp = tid >> 5, lane = tid & 31;
    if (lane == 0) { rs_[warp] = s; rss_[warp] = ss; }
    __syncthreads();
    if (tid == 0) {
        float S = 0.f, SS = 0.f;
        #pragma unroll
        for (int i = 0; i < 8; i++) { S += rs_[i]; SS += rss_[i]; }
        float mu  = S * (1.0f / EMB);
        float var = SS * (1.0f / EMB) - mu * mu;
        mu_s = mu;
        rstd_s = rsqrtf(var + 1e-5f);
    }
    __syncthreads();
    float mu = mu_s, r = rstd_s;
    float4 gv = ((const float4*)lg)[tid];
    float4 bv = ((const float4*)lb)[tid];
    __half2* orow = (__half2*)(lnout + (size_t)row * EMB);
    orow[2 * tid]     = __floats2half2_rn((v.x - mu) * r * gv.x + bv.x,
                                          (v.y - mu) * r * gv.y + bv.y);
    orow[2 * tid + 1] = __floats2half2_rn((v.z - mu) * r * gv.z + bv.z,
                                          (v.w - mu) * r * gv.w + bv.w);
}

// ---------------------------------------------------------------------------
// LayerNorm (standalone, for LN2): float in -> half out
// ---------------------------------------------------------------------------
__global__ __launch_bounds__(256)
void ln_kernel(const float* __restrict__ x, const float* __restrict__ g,
               const float* __restrict__ b, __half* __restrict__ out)
{
    int row = blockIdx.x;
    int t   = threadIdx.x;
    const float4* xr = (const float4*)(x + (size_t)row * EMB);
    float4 v = xr[t];
    float s  = v.x + v.y + v.z + v.w;
    float ss = v.x * v.x + v.y * v.y + v.z * v.z + v.w * v.w;
    #pragma unroll
    for (int o = 16; o; o >>= 1) {
        s  += __shfl_xor_sync(0xffffffffu, s,  o);
        ss += __shfl_xor_sync(0xffffffffu, ss, o);
    }
    __shared__ float rs_[8], rss_[8];
    __shared__ float mu_s, rstd_s;
    int warp = t >> 5, lane = t & 31;
    if (lane == 0) { rs_[warp] = s; rss_[warp] = ss; }
    __syncthreads();
    if (t == 0) {
        float S = 0.f, SS = 0.f;
        #pragma unroll
        for (int i = 0; i < 8; i++) { S += rs_[i]; SS += rss_[i]; }
        float mu  = S * (1.0f / EMB);
        float var = SS * (1.0f / EMB) - mu * mu;
        mu_s = mu;
        rstd_s = rsqrtf(var + 1e-5f);
    }
    __syncthreads();
    float mu = mu_s, r = rstd_s;
    float4 gv = ((const float4*)g)[t];
    float4 bv = ((const float4*)b)[t];
    __half2* orow = (__half2*)(out + (size_t)row * EMB);
    orow[2 * t]     = __floats2half2_rn((v.x - mu) * r * gv.x + bv.x,
                                        (v.y - mu) * r * gv.y + bv.y);
    orow[2 * t + 1] = __floats2half2_rn((v.z - mu) * r * gv.z + bv.z,
                                        (v.w - mu) * r * gv.w + bv.w);
}

// ---------------------------------------------------------------------------
// fp16 mma GEMM: CTA 128x128, 256 threads (8 warps, warp tile 64x32),
// BK=64, 3-stage cp.async, ONE barrier per chunk, 2 CTAs/SM.
// ---------------------------------------------------------------------------
#define G5_STRIDE 72
#define G5_ATILE (128 * G5_STRIDE * 2)   // 18432 B
#define G5_STAGE (2 * G5_ATILE)          // 36864 B (A+B)
#define G5_SMEM  (3 * G5_STAGE)          // 110592 B -> 2 CTAs/SM

template<bool GELU, bool HALF_OUT>
__global__ __launch_bounds__(256, 2)
void gemm_h_kernel(const __half* __restrict__ A, const __half* __restrict__ Bt,
                   const float* __restrict__ bias, const float* __restrict__ res,
                   void* __restrict__ Cv, int N_, int K_)
{
    extern __shared__ char smem[];
    const uint32_t sb = smem_u32(smem);
    int tid  = threadIdx.x;
    int lane = tid & 31, warp = tid >> 5;
    int wm = warp >> 2;
    int wn = warp & 3;
    int rowBase = blockIdx.y * 128;
    int colBase = blockIdx.x * 128;
    const int C_CHUNKS = K_ >> 6;

    auto load_chunk = [&](int c, int st) {
        int k0 = c << 6;
        uint32_t aB = sb + st * G5_STAGE;
        uint32_t bB = aB + G5_ATILE;
        #pragma unroll
        for (int s = 0; s < 4; s++) {
            int idx = tid + s * 256;
            int r = idx >> 3, ch = idx & 7;
            cp16(aB + (uint32_t)(r * G5_STRIDE + ch * 8) * 2,
                 A + (size_t)(rowBase + r) * K_ + k0 + ch * 8);
        }
        #pragma unroll
        for (int s = 0; s < 4; s++) {
            int idx = tid + s * 256;
            int r = idx >> 3, ch = idx & 7;
            cp16(bB + (uint32_t)(r * G5_STRIDE + ch * 8) * 2,
                 Bt + (size_t)(colBase + r) * K_ + k0 + ch * 8);
        }
        cp_commit();
    };

    float acc[4][4][4];
    #pragma unroll
    for (int i = 0; i < 4; i++)
        #pragma unroll
        for (int j = 0; j < 4; j++)
            #pragma unroll
            for (int r = 0; r < 4; r++) acc[i][j][r] = 0.f;

    load_chunk(0, 0);
    load_chunk(1, 1);

    for (int c = 0; c < C_CHUNKS; c++) {
        cp_wait<1>();
        __syncthreads();
        if (c + 2 < C_CHUNKS) load_chunk(c + 2, (c + 2) % 3);
        else cp_commit();

        uint32_t aBase = sb + (c % 3) * G5_STAGE;
        uint32_t bBase = aBase + G5_ATILE;

        #pragma unroll
        for (int ks = 0; ks < 4; ks++) {
            int k0 = ks * 16;
            uint32_t a[4][4];
            #pragma unroll
            for (int mt = 0; mt < 4; mt++) {
                uint32_t addr = aBase +
                    (uint32_t)((wm * 64 + mt * 16 + (lane & 15)) * G5_STRIDE
                               + k0 + ((lane >> 4) << 3)) * 2;
                ldsm_x4(a[mt][0], a[mt][1], a[mt][2], a[mt][3], addr);
            }
            uint32_t bf[4][2];
            {
                int n = wn * 32 + ((lane >> 4) << 3) + (lane & 7);
                int koff = ((lane >> 3) & 1) << 3;
                ldsm_x4(bf[0][0], bf[0][1], bf[1][0], bf[1][1],
                        bBase + (uint32_t)(n * G5_STRIDE + k0 + koff) * 2);
                ldsm_x4(bf[2][0], bf[2][1], bf[3][0], bf[3][1],
                        bBase + (uint32_t)((n + 16) * G5_STRIDE + k0 + koff) * 2);
            }
            #pragma unroll
            for (int mt = 0; mt < 4; mt++)
                #pragma unroll
                for (int nt = 0; nt < 4; nt++)
                    mma_f16(acc[mt][nt][0], acc[mt][nt][1], acc[mt][nt][2], acc[mt][nt][3],
                            a[mt][0], a[mt][1], a[mt][2], a[mt][3],
                            bf[nt][0], bf[nt][1]);
        }
    }

    int lq = lane >> 2, lr = lane & 3;
    __half* Ch = (__half*)Cv;
    float*  Cf = (float*)Cv;
    #pragma unroll
    for (int mt = 0; mt < 4; mt++) {
        int row0 = rowBase + wm * 64 + mt * 16 + lq;
        #pragma unroll
        for (int nt = 0; nt < 4; nt++) {
            int col = colBase + wn * 32 + nt * 8 + lr * 2;
            float2 p0 = make_float2(acc[mt][nt][0], acc[mt][nt][1]);
            float2 p1 = make_float2(acc[mt][nt][2], acc[mt][nt][3]);
            if (bias) {
                float2 bv = *(const float2*)(bias + col);
                p0.x += bv.x; p0.y += bv.y;
                p1.x += bv.x; p1.y += bv.y;
            }
            if (res) {
                float2 r0 = *(const float2*)(res + (size_t)row0 * N_ + col);
                float2 r1 = *(const float2*)(res + (size_t)(row0 + 8) * N_ + col);
                p0.x += r0.x; p0.y += r0.y;
                p1.x += r1.x; p1.y += r1.y;
            }
            if (GELU) {
                p0.x = gelu_fast(p0.x);
                p0.y = gelu_fast(p0.y);
                p1.x = gelu_fast(p1.x);
                p1.y = gelu_fast(p1.y);
            }
            if (HALF_OUT) {
                *(__half2*)(Ch + (size_t)row0 * N_ + col) = __floats2half2_rn(p0.x, p0.y);
                *(__half2*)(Ch + (size_t)(row0 + 8) * N_ + col) = __floats2half2_rn(p1.x, p1.y);
            } else {
                *(float2*)(Cf + (size_t)row0 * N_ + col) = p0;
                *(float2*)(Cf + (size_t)(row0 + 8) * N_ + col) = p1;
            }
        }
    }
}

// ---------------------------------------------------------------------------
// fp16 flash attention, cp.async double-buffered K/V, 2 Q-tiles per CTA.
// ---------------------------------------------------------------------------
#define AHS 72
#define AKV (64 * AHS)
#define AH_SMEM (6 * AKV * 2)             // 55296 B

__global__ __launch_bounds__(128)
void attn_h_kernel(const __half* __restrict__ QKV, __half* __restrict__ Out)
{
    extern __shared__ char smraw[];
    __half* sm = (__half*)smraw;
    __half* Qs = sm;
    __half* Ks = sm + AKV;
    __half* Vs = sm + 3 * AKV;
    __half* Ps = sm + 5 * AKV;
    const uint32_t sQ = smem_u32(Qs), sK0 = smem_u32(Ks), sV0 = smem_u32(Vs),
                   sP = smem_u32(Ps);

    int qb0 = blockIdx.x, h = blockIdx.y, bb = blockIdx.z;
    int tid = threadIdx.x;
    int lane = tid & 31, warp = tid >> 5;
    int lq = lane >> 2, lr = lane & 3;

    const __half* Qp = QKV + h * HEADD;
    const __half* Kp = QKV + EMB + h * HEADD;
    const __half* Vp = QKV + 2 * EMB + h * HEADD;

    auto load_kv = [&](int jt, int b) {
        size_t kbase = (size_t)(bb * TSEQ + jt * 64) * QKV_N;
        uint32_t kB = sK0 + (uint32_t)(b * AKV) * 2;
        uint32_t vB = sV0 + (uint32_t)(b * AKV) * 2;
        #pragma unroll
        for (int s = 0; s < 4; s++) {
            int idx = tid + s * 128;
            int r = idx >> 3, ch = idx & 7;
            cp16(kB + (uint32_t)(r * AHS + ch * 8) * 2,
                 Kp + kbase + (size_t)r * QKV_N + ch * 8);
            cp16(vB + (uint32_t)(r * AHS + ch * 8) * 2,
                 Vp + kbase + (size_t)r * QKV_N + ch * 8);
        }
        cp_commit();
    };

    const uint32_t sPw = sP + (uint32_t)(warp * 16 * AHS) * 2;
    __half* prow = Ps + warp * 16 * AHS;

    #pragma unroll
    for (int rep = 0; rep < 2; rep++) {
        int qb = rep ? (TSEQ / 64 - 1 - qb0) : qb0;

        __syncthreads();

        size_t qbase = (size_t)(bb * TSEQ + qb * 64) * QKV_N;
        #pragma unroll
        for (int s = 0; s < 4; s++) {
            int idx = tid + s * 128;
            int r = idx >> 3, ch = idx & 7;
            *(float4*)(Qs + r * AHS + ch * 8) =
                *(const float4*)(Qp + qbase + (size_t)r * QKV_N + ch * 8);
        }
        load_kv(0, 0);

        float m0 = -CUDART_INF_F, m1 = -CUDART_INF_F;
        float l0 = 0.f, l1 = 0.f;
        float o[8][4];
        #pragma unroll
        for (int nt = 0; nt < 8; nt++)
            #pragma unroll
            for (int r = 0; r < 4; r++) o[nt][r] = 0.f;

        for (int jt = 0; jt <= qb; jt++) {
            cp_wait<0>();
            __syncthreads();
            if (jt < qb) load_kv(jt + 1, (jt + 1) & 1);

            uint32_t sK = sK0 + (uint32_t)((jt & 1) * AKV) * 2;
            uint32_t sV = sV0 + (uint32_t)((jt & 1) * AKV) * 2;

            float s[8][4];
            #pragma unroll
            for (int nt = 0; nt < 8; nt++)
                #pragma unroll
                for (int r = 0; r < 4; r++) s[nt][r] = 0.f;

            #pragma unroll
            for (int ks = 0; ks < 4; ks++) {
                int k0 = ks * 16;
                uint32_t a0, a1, a2, a3;
                ldsm_x4(a0, a1, a2, a3,
                        sQ + (uint32_t)((warp * 16 + (lane & 15)) * AHS
                                        + k0 + ((lane >> 4) << 3)) * 2);
                #pragma unroll
                for (int np = 0; np < 4; np++) {
                    int n = np * 16 + ((lane >> 4) << 3) + (lane & 7);
                    int koff = ((lane >> 3) & 1) << 3;
                    uint32_t b0, b1, b2, b3;
                    ldsm_x4(b0, b1, b2, b3,
                            sK + (uint32_t)(n * AHS + k0 + koff) * 2);
                    mma_f16(s[np * 2][0], s[np * 2][1], s[np * 2][2], s[np * 2][3],
                            a0, a1, a2, a3, b0, b1);
                    mma_f16(s[np * 2 + 1][0], s[np * 2 + 1][1], s[np * 2 + 1][2], s[np * 2 + 1][3],
                            a0, a1, a2, a3, b2, b3);
                }
            }

            const float scale = 0.125f;
            bool diag = (jt == qb);
            int row0 = warp * 16 + lq;
            #pragma unroll
            for (int nt = 0; nt < 8; nt++) {
                int col = nt * 8 + 2 * lr;
                s[nt][0] *= scale; s[nt][1] *= scale;
                s[nt][2] *= scale; s[nt][3] *= scale;
                if (diag) {
                    if (col     > row0)     s[nt][0] = -CUDART_INF_F;
                    if (col + 1 > row0)     s[nt][1] = -CUDART_INF_F;
                    if (col     > row0 + 8) s[nt][2] = -CUDART_INF_F;
                    if (col + 1 > row0 + 8) s[nt][3] = -CUDART_INF_F;
                }
            }

            {
                float rm = -CUDART_INF_F;
                #pragma unroll
                for (int nt = 0; nt < 8; nt++) rm = fmaxf(rm, fmaxf(s[nt][0], s[nt][1]));
                rm = fmaxf(rm, __shfl_xor_sync(0xffffffffu, rm, 1));
                rm = fmaxf(rm, __shfl_xor_sync(0xffffffffu, rm, 2));
                float mn = fmaxf(m0, rm);
                float alpha = __expf(m0 - mn);
                float ps = 0.f;
                #pragma unroll
                for (int nt = 0; nt < 8; nt++) {
                    s[nt][0] = __expf(s[nt][0] - mn);
                    s[nt][1] = __expf(s[nt][1] - mn);
                    ps += s[nt][0] + s[nt][1];
                }
                ps += __shfl_xor_sync(0xffffffffu, ps, 1);
                ps += __shfl_xor_sync(0xffffffffu, ps, 2);
                l0 = l0 * alpha + ps;
                m0 = mn;
                #pragma unroll
                for (int nt = 0; nt < 8; nt++) { o[nt][0] *= alpha; o[nt][1] *= alpha; }
            }
            {
                float rm = -CUDART_INF_F;
                #pragma unroll
                for (int nt = 0; nt < 8; nt++) rm = fmaxf(rm, fmaxf(s[nt][2], s[nt][3]));
                rm = fmaxf(rm, __shfl_xor_sync(0xffffffffu, rm, 1));
                rm = fmaxf(rm, __shfl_xor_sync(0xffffffffu, rm, 2));
                float mn = fmaxf(m1, rm);
                float alpha = __expf(m1 - mn);
                float ps = 0.f;
                #pragma unroll
                for (int nt = 0; nt < 8; nt++) {
                    s[nt][2] = __expf(s[nt][2] - mn);
                    s[nt][3] = __expf(s[nt][3] - mn);
                    ps += s[nt][2] + s[nt][3];
                }
                ps += __shfl_xor_sync(0xffffffffu, ps, 1);
                ps += __shfl_xor_sync(0xffffffffu, ps, 2);
                l1 = l1 * alpha + ps;
                m1 = mn;
                #pragma unroll
                for (int nt = 0; nt < 8; nt++) { o[nt][2] *= alpha; o[nt][3] *= alpha; }
            }

            #pragma unroll
            for (int nt = 0; nt < 8; nt++) {
                *(__half2*)(prow + lq * AHS + nt * 8 + 2 * lr) =
                    __floats2half2_rn(s[nt][0], s[nt][1]);
                *(__half2*)(prow + (lq + 8) * AHS + nt * 8 + 2 * lr) =
                    __floats2half2_rn(s[nt][2], s[nt][3]);
            }
            __syncwarp();

            #pragma unroll
            for (int ks = 0; ks < 4; ks++) {
                int k0 = ks * 16;
                uint32_t a0, a1, a2, a3;
                ldsm_x4(a0, a1, a2, a3,
                        sPw + (uint32_t)((lane & 15) * AHS + k0 + ((lane >> 4) << 3)) * 2);
                #pragma unroll
                for (int dp = 0; dp < 4; dp++) {
                    uint32_t b0, b1, b2, b3;
                    ldsm_x4t(b0, b1, b2, b3,
                             sV + (uint32_t)((k0 + (lane & 15)) * AHS
                                             + dp * 16 + ((lane >> 4) << 3)) * 2);
                    mma_f16(o[dp * 2][0], o[dp * 2][1], o[dp * 2][2], o[dp * 2][3],
                            a0, a1, a2, a3, b0, b1);
                    mma_f16(o[dp * 2 + 1][0], o[dp * 2 + 1][1], o[dp * 2 + 1][2], o[dp * 2 + 1][3],
                            a0, a1, a2, a3, b2, b3);
                }
            }
            __syncwarp();
        }

        float inv0 = 1.0f / l0, inv1 = 1.0f / l1;
        size_t r0 = (size_t)(bb * TSEQ + qb * 64 + warp * 16 + lq);
        size_t r1 = r0 + 8;
        #pragma unroll
        for (int nt = 0; nt < 8; nt++) {
            int col = h * HEADD + nt * 8 + 2 * lr;
            *(__half2*)(Out + r0 * EMB + col) =
                __floats2half2_rn(o[nt][0] * inv0, o[nt][1] * inv0);
            *(__half2*)(Out + r1 * EMB + col) =
                __floats2half2_rn(o[nt][2] * inv1, o[nt][3] * inv1);
        }
    }
}

// ---------------------------------------------------------------------------
// Launch
// ---------------------------------------------------------------------------
extern "C" void kernel_launch(void* const* d_in, const int* in_sizes, int n_in,
                              void* d_out, int out_size)
{
    const float* x      = (const float*)d_in[0];
    const float* ln1_g  = (const float*)d_in[1];
    const float* ln1_b  = (const float*)d_in[2];
    const float* wq     = (const float*)d_in[3];
    const float* wk     = (const float*)d_in[4];
    const float* wv     = (const float*)d_in[5];
    const float* w_proj = (const float*)d_in[6];
    const float* b_proj = (const float*)d_in[7];
    const float* ln2_g  = (const float*)d_in[8];
    const float* ln2_b  = (const float*)d_in[9];
    const float* w1     = (const float*)d_in[10];
    const float* b1     = (const float*)d_in[11];
    const float* w2     = (const float*)d_in[12];
    const float* b2     = (const float*)d_in[13];
    float* out = (float*)d_out;

    __half *h, *qkv, *attn, *mid;
    float  *out1;
    __half *wqkvT, *wpT, *w1T, *w2T;
    cudaGetSymbolAddress((void**)&h,     g_h);
    cudaGetSymbolAddress((void**)&qkv,   g_qkv);
    cudaGetSymbolAddress((void**)&attn,  g_attn);
    cudaGetSymbolAddress((void**)&out1,  g_out1);
    cudaGetSymbolAddress((void**)&mid,   g_mid);
    cudaGetSymbolAddress((void**)&wqkvT, g_wqkvT);
    cudaGetSymbolAddress((void**)&wpT,   g_wpT);
    cudaGetSymbolAddress((void**)&w1T,   g_w1T);
    cudaGetSymbolAddress((void**)&w2T,   g_w2T);

    cudaFuncSetAttribute(gemm_h_kernel<false, false>,
                         cudaFuncAttributeMaxDynamicSharedMemorySize, G5_SMEM);
    cudaFuncSetAttribute(gemm_h_kernel<false, true>,
                         cudaFuncAttributeMaxDynamicSharedMemorySize, G5_SMEM);
    cudaFuncSetAttribute(gemm_h_kernel<true, true>,
                         cudaFuncAttributeMaxDynamicSharedMemorySize, G5_SMEM);
    cudaFuncSetAttribute(attn_h_kernel,
                         cudaFuncAttributeMaxDynamicSharedMemorySize, AH_SMEM);

    // 0. Prep: 6 transposes + LN1 in one launch
    PrepArgs pa;
    pa.in[0] = wq;     pa.out[0] = wqkvT;                         pa.K[0] = EMB;   pa.N[0] = EMB;
    pa.in[1] = wk;     pa.out[1] = wqkvT + (size_t)EMB * EMB;     pa.K[1] = EMB;   pa.N[1] = EMB;
    pa.in[2] = wv;     pa.out[2] = wqkvT + (size_t)2 * EMB * EMB; pa.K[2] = EMB;   pa.N[2] = EMB;
    pa.in[3] = w_proj; pa.out[3] = wpT;                           pa.K[3] = EMB;   pa.N[3] = EMB;
    pa.in[4] = w1;     pa.out[4] = w1T;                           pa.K[4] = EMB;   pa.N[4] = FFDIM;
    pa.in[5] = w2;     pa.out[5] = w2T;                           pa.K[5] = FFDIM; pa.N[5] = EMB;
    int total = 0;
    for (int i = 0; i < 6; i++) {
        pa.off[i] = total;
        total += (pa.N[i] / 32) * (pa.K[i] / 32);
    }
    pa.trans_total = total;
    prep_kernel<<<total + MROWS, 256>>>(pa, x, ln1_g, ln1_b, h);

    // 2. Fused QKV projection
    dim3 gQKV(QKV_N / 128, MROWS / 128);
    gemm_h_kernel<false, true><<<gQKV, 256, G5_SMEM>>>(h, wqkvT, nullptr, nullptr, qkv, QKV_N, EMB);

    // 3. Causal flash attention
    attn_h_kernel<<<dim3(TSEQ / 128, NHEAD, BSZ), 128, AH_SMEM>>>(qkv, attn);

    // 4. out1 = x + attn @ w_proj + b_proj
    dim3 gE(EMB / 128, MROWS / 128);
    gemm_h_kernel<false, false><<<gE, 256, G5_SMEM>>>(attn, wpT, b_proj, x, out1, EMB, EMB);

    // 5. LN2 -> half
    ln_kernel<<<MROWS, 256>>>(out1, ln2_g, ln2_b, h);

    // 6. mid = gelu(h @ w1 + b1)
    dim3 gF(FFDIM / 128, MROWS / 128);
    gemm_h_kernel<true, true><<<gF, 256, G5_SMEM>>>(h, w1T, b1, nullptr, mid, FFDIM, EMB);

    // 7. out = out1 + mid @ w2 + b2
    gemm_h_kernel<false, false><<<gE, 256, G5_SMEM>>>(mid, w2T, b2, out1, out, EMB, FFDIM);
}